// round 8
// baseline (speedup 1.0000x reference)
#include <cuda_runtime.h>
#include <math.h>

typedef unsigned long long u64;
#define B_SZ 32
#define N_PTS 64

// Scratch (static __device__ — no allocation anywhere)
__device__ float g_att[6 * B_SZ * 4096];   // [mat][b][row*64+col]
__device__ float g_agg[B_SZ * N_PTS];      // raw per-(b,i) sums (undivided)

// ---------- packed f32x2 helpers ----------
__device__ __forceinline__ u64 f2mul(u64 a, u64 b) {
    u64 r; asm("mul.rn.f32x2 %0, %1, %2;" : "=l"(r) : "l"(a), "l"(b)); return r;
}
__device__ __forceinline__ u64 f2fma(u64 a, u64 b, u64 c) {
    u64 r; asm("fma.rn.f32x2 %0, %1, %2, %3;" : "=l"(r) : "l"(a), "l"(b), "l"(c)); return r;
}
__device__ __forceinline__ u64 packf2(float lo, float hi) {
    u64 r; asm("mov.b64 %0, {%1, %2};" : "=l"(r)
               : "r"(__float_as_uint(lo)), "r"(__float_as_uint(hi)));
    return r;
}
__device__ __forceinline__ void unpackf2(u64 v, float& lo, float& hi) {
    unsigned a, b; asm("mov.b64 {%0, %1}, %2;" : "=r"(a), "=r"(b) : "l"(v));
    lo = __uint_as_float(a); hi = __uint_as_float(b);
}
__device__ __forceinline__ float frcp(float x) {
    float r; asm("rcp.approx.ftz.f32 %0, %1;" : "=f"(r) : "f"(x)); return r;
}

// ---------- Kernel A: projections + 6 att matrices (one block per batch) ----------
__global__ void __launch_bounds__(256) att_kernel(
    const float* __restrict__ pc,
    const float* __restrict__ Wq,  const float* __restrict__ bq,
    const float* __restrict__ Wk1, const float* __restrict__ bk1,
    const float* __restrict__ Wk2, const float* __restrict__ bk2,
    const float* __restrict__ Wk3, const float* __restrict__ bk3)
{
    extern __shared__ float sm[];
    float* Q  = sm;                 // [64][65] pad
    float* Kj = sm + 64 * 65;
    float* Kk = sm + 2 * 64 * 65;
    float* Kl = sm + 3 * 64 * 65;
    const int b = blockIdx.x, t = threadIdx.x;

    for (int idx = t; idx < 4096; idx += 256) {
        const int n = idx >> 6, d = idx & 63;
        const float* p = pc + (b * 64 + n) * 3;
        const float px = p[0], py = p[1], pz = p[2];
        Q [n * 65 + d] = bq [d] + px * Wq [d] + py * Wq [64 + d] + pz * Wq [128 + d];
        Kj[n * 65 + d] = bk1[d] + px * Wk1[d] + py * Wk1[64 + d] + pz * Wk1[128 + d];
        Kk[n * 65 + d] = bk2[d] + px * Wk2[d] + py * Wk2[64 + d] + pz * Wk2[128 + d];
        Kl[n * 65 + d] = bk3[d] + px * Wk3[d] + py * Wk3[64 + d] + pz * Wk3[128 + d];
    }
    __syncthreads();

    const float scale = 0.125f;  // rsqrt(64)
    for (int idx = t; idx < 4096; idx += 256) {
        const int r = idx >> 6, c = idx & 63;
        float s0=0.f, s1=0.f, s2=0.f, s3=0.f, s4=0.f, s5=0.f;
        #pragma unroll 8
        for (int d = 0; d < 64; ++d) {
            const float qr  = Q [r * 65 + d];   // broadcast (r uniform in warp)
            const float kjr = Kj[r * 65 + d];
            const float kkr = Kk[r * 65 + d];
            const float kjc = Kj[c * 65 + d];   // stride-65 conflict-free
            const float kkc = Kk[c * 65 + d];
            const float klc = Kl[c * 65 + d];
            s0 += qr  * kjc;  s1 += qr  * kkc;  s2 += qr  * klc;
            s3 += kjr * kkc;  s4 += kjr * klc;  s5 += kkr * klc;
        }
        g_att[(0 * B_SZ + b) * 4096 + idx] = s0 * scale;  // att_ij: Q.Kj
        g_att[(1 * B_SZ + b) * 4096 + idx] = s1 * scale;  // att_ik: Q.Kk
        g_att[(2 * B_SZ + b) * 4096 + idx] = s2 * scale;  // att_il: Q.Kl
        g_att[(3 * B_SZ + b) * 4096 + idx] = s3 * scale;  // att_jk
        g_att[(4 * B_SZ + b) * 4096 + idx] = s4 * scale;  // att_jl
        g_att[(5 * B_SZ + b) * 4096 + idx] = s5 * scale;  // att_kl
    }
}

// ---------- Main kernel: one block per (i, b) ----------
__global__ void __launch_bounds__(256, 2) main_kernel(const float* __restrict__ pc)
{
    extern __shared__ float sm[];
    float* Xt  = sm;                  // [k:64][j pad 66]  = exp(-(a_ij[j]+a_jk[j,k]))
    float* Yt  = sm + 64 * 66;        // [l:64][j:64]      = exp(-a_jl[j,l])
    float* Zs  = Yt + 4096;           // [l:64][k:64]      = exp(-(a_ik[k]+a_il[l]+a_kl[k,l]))
    float* dpx = Zs + 4096;           // [64]
    float* dpy = dpx + 64;
    float* dpz = dpy + 64;
    __shared__ float red[8];

    const int i = blockIdx.x, b = blockIdx.y, t = threadIdx.x;

    const float* aqj = g_att + (0 * B_SZ + b) * 4096;
    const float* aqk = g_att + (1 * B_SZ + b) * 4096;
    const float* aql = g_att + (2 * B_SZ + b) * 4096;
    const float* ajk = g_att + (3 * B_SZ + b) * 4096;
    const float* ajl = g_att + (4 * B_SZ + b) * 4096;
    const float* akl = g_att + (5 * B_SZ + b) * 4096;

    for (int idx = t; idx < 4096; idx += 256) {
        const int j = idx >> 6, k = idx & 63;
        Xt[k * 66 + j] = __expf(-(aqj[i * 64 + j] + ajk[idx]));
    }
    for (int idx = t; idx < 4096; idx += 256) {
        const int j = idx >> 6, l = idx & 63;
        Yt[l * 64 + j] = __expf(-ajl[idx]);
    }
    for (int idx = t; idx < 4096; idx += 256) {
        const int k = idx >> 6, l = idx & 63;
        Zs[l * 64 + k] = __expf(-(aqk[i * 64 + k] + aql[i * 64 + l] + akl[idx]));
    }
    if (t < 64) {
        const float* p  = pc + (b * 64 + t) * 3;
        const float* pi = pc + (b * 64 + i) * 3;
        dpx[t] = p[0] - pi[0]; dpy[t] = p[1] - pi[1]; dpz[t] = p[2] - pi[2];
    }
    __syncthreads();

    // k = lane + (warp&1)*32 ; l group of 16 from warp>>1 ; all j.
    const int w = t >> 5, lane = t & 31;
    const int k = lane + ((w & 1) << 5);
    const int lbase = (w >> 1) << 4;

    const float dkx = dpx[k], dky = dpy[k], dkz = dpz[k];
    const u64 ONE2 = packf2(1.0f, 1.0f);
    u64 acc = packf2(0.0f, 0.0f);

    for (int jt = 0; jt < 4; ++jt) {
        const int j0 = jt << 4;
        u64 dxp[8], dyp[8], dzp[8];
        #pragma unroll
        for (int u = 0; u < 8; ++u) {   // disp j-tile in registers (broadcast LDS.64)
            dxp[u] = *(const u64*)(dpx + j0 + 2 * u);
            dyp[u] = *(const u64*)(dpy + j0 + 2 * u);
            dzp[u] = *(const u64*)(dpz + j0 + 2 * u);
        }
        for (int p = 0; p < 16; ++p) {
            const int l = lbase + p;
            const float dlx = dpx[l], dly = dpy[l], dlz = dpz[l];  // broadcast
            const float cx = dky * dlz - dkz * dly;   // cross(disp_k, disp_l)
            const float cy = dkz * dlx - dkx * dlz;
            const float cz = dkx * dly - dky * dlx;
            const float zv = Zs[l * 64 + k];
            const u64 cxp = packf2(cx, cx), cyp = packf2(cy, cy), czp = packf2(cz, cz);
            const u64 zp  = packf2(zv, zv);
            const float* xrow = Xt + k * 66 + j0;
            const float* yrow = Yt + l * 64 + j0;
            #pragma unroll
            for (int u = 0; u < 8; ++u) {             // 2 j per iter, packed
                const u64 Xp = *(const u64*)(xrow + 2 * u);
                const u64 Yp = *(const u64*)(yrow + 2 * u);   // broadcast
                const u64 m  = f2mul(Xp, Yp);
                const u64 dd = f2fma(m, zp, ONE2);    // 1 + e^{-energy}
                float d0, d1; unpackf2(dd, d0, d1);
                const float r0 = frcp(d0);            // gate — MUFU, the binder
                const float r1 = frcp(d1);
                u64 det = f2mul(dxp[u], cxp);
                det = f2fma(dyp[u], cyp, det);
                det = f2fma(dzp[u], czp, det);
                const u64 q = f2mul(det, det);
                acc = f2fma(q, packf2(r0, r1), acc);  // += gate * det^2
            }
        }
    }

    float alo, ahi; unpackf2(acc, alo, ahi);
    float s = alo + ahi;
    #pragma unroll
    for (int off = 16; off > 0; off >>= 1)
        s += __shfl_xor_sync(0xffffffffu, s, off);
    if (lane == 0) red[w] = s;
    __syncthreads();
    if (t == 0) {
        float tot = 0.f;
        #pragma unroll
        for (int q = 0; q < 8; ++q) tot += red[q];
        g_agg[b * 64 + i] = tot;
    }
}

// ---------- Epilogue: pool over anchors + tiny MLP ----------
__global__ void final_kernel(const float* __restrict__ W1, const float* __restrict__ b1,
                             const float* __restrict__ W2, const float* __restrict__ b2,
                             float* __restrict__ out)
{
    const int b = threadIdx.x;
    if (b >= B_SZ) return;
    float pooled = 0.f;
    for (int i = 0; i < 64; ++i) pooled += g_agg[b * 64 + i];
    pooled *= (1.0f / (64.0f * 262144.0f));   // /N^3 then mean over N anchors
    float o = b2[0];
    for (int j = 0; j < 32; ++j) {
        const float x = pooled * W1[j] + b1[j];
        const float c = 0.7978845608028654f * (x + 0.044715f * x * x * x);
        const float g = 0.5f * x * (1.0f + tanhf(c));   // tanh-approx gelu
        o += g * W2[j];
    }
    out[b] = o;
}

extern "C" void kernel_launch(void* const* d_in, const int* in_sizes, int n_in,
                              void* d_out, int out_size)
{
    const float* pc  = (const float*)d_in[0];
    const float* Wq  = (const float*)d_in[1];  const float* bq  = (const float*)d_in[2];
    const float* Wk1 = (const float*)d_in[3];  const float* bk1 = (const float*)d_in[4];
    const float* Wk2 = (const float*)d_in[5];  const float* bk2 = (const float*)d_in[6];
    const float* Wk3 = (const float*)d_in[7];  const float* bk3 = (const float*)d_in[8];
    const float* W1  = (const float*)d_in[9];  const float* b1  = (const float*)d_in[10];
    const float* W2  = (const float*)d_in[11]; const float* b2  = (const float*)d_in[12];

    const int smemA = 4 * 64 * 65 * sizeof(float);          // 66560 B
    const int smemM = (64 * 66 + 4096 + 4096 + 192) * (int)sizeof(float);  // 50432 B
    cudaFuncSetAttribute(att_kernel,  cudaFuncAttributeMaxDynamicSharedMemorySize, smemA);
    cudaFuncSetAttribute(main_kernel, cudaFuncAttributeMaxDynamicSharedMemorySize, smemM);

    att_kernel<<<B_SZ, 256, smemA>>>(pc, Wq, bq, Wk1, bk1, Wk2, bk2, Wk3, bk3);
    main_kernel<<<dim3(N_PTS, B_SZ), 256, smemM>>>(pc);
    final_kernel<<<1, 32>>>(W1, b1, W2, b2, (float*)d_out);
}

// round 9
// speedup vs baseline: 1.1931x; 1.1931x over previous
#include <cuda_runtime.h>
#include <math.h>

typedef unsigned long long u64;
#define B_SZ 32
#define N_PTS 64

// Scratch (static __device__ — no allocation anywhere)
// mats 0..2: raw scaled att rows (att_ij, att_ik, att_il), row-major [i][n]
// mats 3..5: exp(-att) TRANSPOSED: [k][j]=exp(-a_jk), [l][j]=exp(-a_jl), [l][k]=exp(-a_kl)
__device__ float g_att[6 * B_SZ * 4096];
__device__ float g_agg[B_SZ * N_PTS];      // raw per-(b,i) sums (undivided)

// ---------- packed f32x2 helpers ----------
__device__ __forceinline__ u64 f2mul(u64 a, u64 b) {
    u64 r; asm("mul.rn.f32x2 %0, %1, %2;" : "=l"(r) : "l"(a), "l"(b)); return r;
}
__device__ __forceinline__ u64 f2fma(u64 a, u64 b, u64 c) {
    u64 r; asm("fma.rn.f32x2 %0, %1, %2, %3;" : "=l"(r) : "l"(a), "l"(b), "l"(c)); return r;
}
__device__ __forceinline__ u64 packf2(float lo, float hi) {
    u64 r; asm("mov.b64 %0, {%1, %2};" : "=l"(r)
               : "r"(__float_as_uint(lo)), "r"(__float_as_uint(hi)));
    return r;
}
__device__ __forceinline__ void unpackf2(u64 v, float& lo, float& hi) {
    unsigned a, b; asm("mov.b64 {%0, %1}, %2;" : "=r"(a), "=r"(b) : "l"(v));
    lo = __uint_as_float(a); hi = __uint_as_float(b);
}
__device__ __forceinline__ float frcp(float x) {
    float r; asm("rcp.approx.ftz.f32 %0, %1;" : "=f"(r) : "f"(x)); return r;
}

// ---------- Kernel A: projections + 6 att matrices ----------
// grid (8, B_SZ): blockIdx.x = row chunk of 8, blockIdx.y = batch.
// Each warp owns one output row r; each lane owns columns (lane, lane+32).
__global__ void __launch_bounds__(256) att_kernel(
    const float* __restrict__ pc,
    const float* __restrict__ Wq,  const float* __restrict__ bq,
    const float* __restrict__ Wk1, const float* __restrict__ bk1,
    const float* __restrict__ Wk2, const float* __restrict__ bk2,
    const float* __restrict__ Wk3, const float* __restrict__ bk3)
{
    extern __shared__ float sm[];
    float* Q  = sm;                 // [64][65] pad
    float* Kj = sm + 64 * 65;
    float* Kk = sm + 2 * 64 * 65;
    float* Kl = sm + 3 * 64 * 65;
    const int b = blockIdx.y, t = threadIdx.x;
    const int r0 = blockIdx.x << 3;

    // Projections for all 64 points (redundant across the 8 row-chunk blocks — cheap)
    for (int idx = t; idx < 4096; idx += 256) {
        const int n = idx >> 6, d = idx & 63;
        const float* p = pc + (b * 64 + n) * 3;
        const float px = p[0], py = p[1], pz = p[2];
        Q [n * 65 + d] = bq [d] + px * Wq [d] + py * Wq [64 + d] + pz * Wq [128 + d];
        Kj[n * 65 + d] = bk1[d] + px * Wk1[d] + py * Wk1[64 + d] + pz * Wk1[128 + d];
        Kk[n * 65 + d] = bk2[d] + px * Wk2[d] + py * Wk2[64 + d] + pz * Wk2[128 + d];
        Kl[n * 65 + d] = bk3[d] + px * Wk3[d] + py * Wk3[64 + d] + pz * Wk3[128 + d];
    }
    __syncthreads();

    const float scale = 0.125f;  // rsqrt(64)
    const int w = t >> 5, lane = t & 31;
    const int r = r0 + w;
    const int c0 = lane, c1 = lane + 32;

    float a0=0.f,a1=0.f,a2=0.f,a3=0.f,a4=0.f,a5=0.f;     // col c0
    float b0=0.f,b1=0.f,b2=0.f,b3=0.f,b4=0.f,b5=0.f;     // col c1
    #pragma unroll 8
    for (int d = 0; d < 64; ++d) {
        const float qr  = Q [r * 65 + d];    // broadcast (r warp-uniform)
        const float kjr = Kj[r * 65 + d];
        const float kkr = Kk[r * 65 + d];
        const float kj0 = Kj[c0 * 65 + d];   // lane-varying, bank (lane+d)%32: clean
        const float kk0 = Kk[c0 * 65 + d];
        const float kl0 = Kl[c0 * 65 + d];
        const float kj1 = Kj[c1 * 65 + d];
        const float kk1 = Kk[c1 * 65 + d];
        const float kl1 = Kl[c1 * 65 + d];
        a0 += qr  * kj0;  a1 += qr  * kk0;  a2 += qr  * kl0;
        a3 += kjr * kk0;  a4 += kjr * kl0;  a5 += kkr * kl0;
        b0 += qr  * kj1;  b1 += qr  * kk1;  b2 += qr  * kl1;
        b3 += kjr * kk1;  b4 += kjr * kl1;  b5 += kkr * kl1;
    }

    float* g0 = g_att + (0 * B_SZ + b) * 4096;
    float* g1 = g_att + (1 * B_SZ + b) * 4096;
    float* g2 = g_att + (2 * B_SZ + b) * 4096;
    float* g3 = g_att + (3 * B_SZ + b) * 4096;
    float* g4 = g_att + (4 * B_SZ + b) * 4096;
    float* g5 = g_att + (5 * B_SZ + b) * 4096;

    // i-dependent mats: raw, row-major (main reads only row i, contiguous)
    g0[r * 64 + c0] = a0 * scale;  g0[r * 64 + c1] = b0 * scale;
    g1[r * 64 + c0] = a1 * scale;  g1[r * 64 + c1] = b1 * scale;
    g2[r * 64 + c0] = a2 * scale;  g2[r * 64 + c1] = b2 * scale;
    // i-independent mats: store exp(-att), transposed so main's fills read contiguously
    g3[c0 * 64 + r] = __expf(-a3 * scale);  g3[c1 * 64 + r] = __expf(-b3 * scale);
    g4[c0 * 64 + r] = __expf(-a4 * scale);  g4[c1 * 64 + r] = __expf(-b4 * scale);
    g5[c0 * 64 + r] = __expf(-a5 * scale);  g5[c1 * 64 + r] = __expf(-b5 * scale);
}

// ---------- Main kernel: one block per (i, b) ----------
__global__ void __launch_bounds__(256, 3) main_kernel(const float* __restrict__ pc)
{
    extern __shared__ float sm[];
    float* Xt  = sm;                  // [k:64][j pad 66] = exp(-(a_ij[j]+a_jk[j,k]))
    float* Yt  = sm + 64 * 66;        // [l:64][j:64]     = exp(-a_jl[j,l])
    float* Zs  = Yt + 4096;           // [l:64][k:64]     = exp(-(a_ik[k]+a_il[l]+a_kl[k,l]))
    float* ej  = Zs + 4096;           // [64] exp(-a_ij[i,j])
    float* ek  = ej + 64;
    float* el  = ek + 64;
    float* dpx = el + 64;             // [64] displacements
    float* dpy = dpx + 64;
    float* dpz = dpy + 64;            // total 12800 floats = 51200 B
    __shared__ float red[8];

    const int i = blockIdx.x, b = blockIdx.y, t = threadIdx.x;

    const float* aqj  = g_att + (0 * B_SZ + b) * 4096 + i * 64;
    const float* aqk  = g_att + (1 * B_SZ + b) * 4096 + i * 64;
    const float* aql  = g_att + (2 * B_SZ + b) * 4096 + i * 64;
    const float* ejkT = g_att + (3 * B_SZ + b) * 4096;   // [k][j]
    const float* ejlT = g_att + (4 * B_SZ + b) * 4096;   // [l][j]
    const float* eklT = g_att + (5 * B_SZ + b) * 4096;   // [l][k]

    if (t < 64)       ej[t]       = __expf(-aqj[t]);
    else if (t < 128) ek[t - 64]  = __expf(-aqk[t - 64]);
    else if (t < 192) el[t - 128] = __expf(-aql[t - 128]);
    if (t < 64) {
        const float* p  = pc + (b * 64 + t) * 3;
        const float* pi = pc + (b * 64 + i) * 3;
        dpx[t] = p[0] - pi[0]; dpy[t] = p[1] - pi[1]; dpz[t] = p[2] - pi[2];
    }
    __syncthreads();

    for (int idx = t; idx < 4096; idx += 256) {           // X = ej[j] * e^{-a_jk}
        const int k = idx >> 6, j = idx & 63;
        Xt[k * 66 + j] = ej[j] * ejkT[idx];
    }
    for (int idx = t; idx < 1024; idx += 256)             // Y straight copy, float4
        ((float4*)Yt)[idx] = ((const float4*)ejlT)[idx];
    for (int idx = t; idx < 4096; idx += 256) {           // Z = ek[k]*el[l]*e^{-a_kl}
        const int k = idx & 63, l = idx >> 6;
        Zs[idx] = ek[k] * (el[l] * eklT[idx]);
    }
    __syncthreads();

    // k = lane + (warp&1)*32 ; l group of 16 from warp>>1 ; all j.
    const int w = t >> 5, lane = t & 31;
    const int k = lane + ((w & 1) << 5);
    const int lbase = (w >> 1) << 4;

    const float dkx = dpx[k], dky = dpy[k], dkz = dpz[k];
    const u64 ONE2 = packf2(1.0f, 1.0f);
    u64 acc = packf2(0.0f, 0.0f);

    for (int jt = 0; jt < 4; ++jt) {
        const int j0 = jt << 4;
        u64 dxp[8], dyp[8], dzp[8];
        #pragma unroll
        for (int u = 0; u < 8; ++u) {   // disp j-tile in registers (broadcast LDS.64)
            dxp[u] = *(const u64*)(dpx + j0 + 2 * u);
            dyp[u] = *(const u64*)(dpy + j0 + 2 * u);
            dzp[u] = *(const u64*)(dpz + j0 + 2 * u);
        }
        for (int p = 0; p < 16; ++p) {
            const int l = lbase + p;
            const float dlx = dpx[l], dly = dpy[l], dlz = dpz[l];  // broadcast
            const float cx = dky * dlz - dkz * dly;   // cross(disp_k, disp_l)
            const float cy = dkz * dlx - dkx * dlz;
            const float cz = dkx * dly - dky * dlx;
            const float zv = Zs[l * 64 + k];          // lane-contiguous
            const u64 cxp = packf2(cx, cx), cyp = packf2(cy, cy), czp = packf2(cz, cz);
            const u64 zp  = packf2(zv, zv);
            const float* xrow = Xt + k * 66 + j0;
            const float* yrow = Yt + l * 64 + j0;
            #pragma unroll
            for (int u = 0; u < 8; ++u) {             // 2 j per iter, packed
                const u64 Xp = *(const u64*)(xrow + 2 * u);   // pad-66: conflict-free
                const u64 Yp = *(const u64*)(yrow + 2 * u);   // broadcast
                const u64 m  = f2mul(Xp, Yp);
                const u64 dd = f2fma(m, zp, ONE2);    // 1 + e^{-energy}
                float d0, d1; unpackf2(dd, d0, d1);
                const float r0 = frcp(d0);            // gate — MUFU, the binder
                const float r1 = frcp(d1);
                u64 det = f2mul(dxp[u], cxp);
                det = f2fma(dyp[u], cyp, det);
                det = f2fma(dzp[u], czp, det);
                const u64 q = f2mul(det, det);
                acc = f2fma(q, packf2(r0, r1), acc);  // += gate * det^2
            }
        }
    }

    float alo, ahi; unpackf2(acc, alo, ahi);
    float s = alo + ahi;
    #pragma unroll
    for (int off = 16; off > 0; off >>= 1)
        s += __shfl_xor_sync(0xffffffffu, s, off);
    if (lane == 0) red[w] = s;
    __syncthreads();
    if (t == 0) {
        float tot = 0.f;
        #pragma unroll
        for (int q = 0; q < 8; ++q) tot += red[q];
        g_agg[b * 64 + i] = tot;
    }
}

// ---------- Epilogue: pool over anchors + tiny MLP ----------
__global__ void final_kernel(const float* __restrict__ W1, const float* __restrict__ b1,
                             const float* __restrict__ W2, const float* __restrict__ b2,
                             float* __restrict__ out)
{
    const int b = threadIdx.x;
    if (b >= B_SZ) return;
    float pooled = 0.f;
    for (int i = 0; i < 64; ++i) pooled += g_agg[b * 64 + i];
    pooled *= (1.0f / (64.0f * 262144.0f));   // /N^3 then mean over N anchors
    float o = b2[0];
    for (int j = 0; j < 32; ++j) {
        const float x = pooled * W1[j] + b1[j];
        const float c = 0.7978845608028654f * (x + 0.044715f * x * x * x);
        const float g = 0.5f * x * (1.0f + tanhf(c));   // tanh-approx gelu
        o += g * W2[j];
    }
    out[b] = o;
}

extern "C" void kernel_launch(void* const* d_in, const int* in_sizes, int n_in,
                              void* d_out, int out_size)
{
    const float* pc  = (const float*)d_in[0];
    const float* Wq  = (const float*)d_in[1];  const float* bq  = (const float*)d_in[2];
    const float* Wk1 = (const float*)d_in[3];  const float* bk1 = (const float*)d_in[4];
    const float* Wk2 = (const float*)d_in[5];  const float* bk2 = (const float*)d_in[6];
    const float* Wk3 = (const float*)d_in[7];  const float* bk3 = (const float*)d_in[8];
    const float* W1  = (const float*)d_in[9];  const float* b1  = (const float*)d_in[10];
    const float* W2  = (const float*)d_in[11]; const float* b2  = (const float*)d_in[12];

    const int smemA = 4 * 64 * 65 * sizeof(float);   // 66560 B
    const int smemM = 12800 * (int)sizeof(float);    // 51200 B
    cudaFuncSetAttribute(att_kernel,  cudaFuncAttributeMaxDynamicSharedMemorySize, smemA);
    cudaFuncSetAttribute(main_kernel, cudaFuncAttributeMaxDynamicSharedMemorySize, smemM);

    att_kernel<<<dim3(8, B_SZ), 256, smemA>>>(pc, Wq, bq, Wk1, bk1, Wk2, bk2, Wk3, bk3);
    main_kernel<<<dim3(N_PTS, B_SZ), 256, smemM>>>(pc);
    final_kernel<<<1, 32>>>(W1, b1, W2, b2, (float*)d_out);
}